// round 14
// baseline (speedup 1.0000x reference)
#include <cuda_runtime.h>
#include <cuda_bf16.h>
#include <math.h>
#include <stdint.h>

#define NCAM 6
#define MID 256
#define DBINS 112
#define HH 32
#define WW 88
#define NPIX 2816
#define NVOX (128*128*16)
#define WHT 576                 // conv tiles; depth tiles at 576..579

__device__ __align__(1024) float g_xf [NCAM*NPIX*MID];
__device__ __align__(1024) float g_dp [NCAM*NPIX*DBINS];
__device__ __align__(1024) float g_gate[NCAM*MID];
__device__ __align__(1024) __nv_bfloat16 g_imgh[NCAM*NPIX*512];
__device__ __align__(1024) __nv_bfloat16 g_imgl[NCAM*NPIX*512];
__device__ __align__(1024) __nv_bfloat16 g_xh[NCAM*NPIX*MID];
__device__ __align__(1024) __nv_bfloat16 g_xl[NCAM*NPIX*MID];
__device__ __align__(1024) __nv_bfloat16 g_yh[NCAM*NPIX*MID];
__device__ __align__(1024) __nv_bfloat16 g_yl[NCAM*NPIX*MID];
__device__ __align__(1024) __nv_bfloat16 g_Wh[(WHT+4)*128*64];
__device__ __align__(1024) __nv_bfloat16 g_Wl[(WHT+4)*128*64];

__device__ __forceinline__ uint32_t smem_u32(const void* p) {
    uint32_t a;
    asm("{ .reg .u64 t; cvta.to.shared.u64 t, %1; cvt.u32.u64 %0, t; }" : "=r"(a) : "l"(p));
    return a;
}
#define SW128(o) ((o) ^ (((o) >> 3) & 0x70))
#define LDM4(r0,r1,r2,r3,addr) \
    asm volatile("ldmatrix.sync.aligned.m8n8.x4.shared.b16 {%0,%1,%2,%3}, [%4];" \
        : "=r"(r0),"=r"(r1),"=r"(r2),"=r"(r3) : "r"(addr))
#define MMA(d,a,b0,b1) \
    asm volatile("mma.sync.aligned.m16n8k16.row.col.f32.bf16.bf16.f32 " \
        "{%0,%1,%2,%3},{%4,%5,%6,%7},{%8,%9},{%0,%1,%2,%3};" \
        : "+f"((d)[0]),"+f"((d)[1]),"+f"((d)[2]),"+f"((d)[3]) \
        : "r"((a)[0]),"r"((a)[1]),"r"((a)[2]),"r"((a)[3]),"r"(b0),"r"(b1))
__device__ __forceinline__ void cpa16(uint32_t dst, const void* src, int sz) {
    asm volatile("cp.async.cg.shared.global [%0], [%1], 16, %2;" :: "r"(dst), "l"(src), "r"(sz) : "memory");
}
#define CPA_COMMIT() asm volatile("cp.async.commit_group;" ::: "memory")
#define CPA_WAIT0()  asm volatile("cp.async.wait_group 0;" ::: "memory")

__device__ __forceinline__ uint32_t pack_hi(float a, float b, uint32_t &lo) {
    const __nv_bfloat16 h0 = __float2bfloat16(a), h1 = __float2bfloat16(b);
    lo = (uint32_t)__bfloat16_as_ushort(__float2bfloat16(a - __bfloat162float(h0)))
       | ((uint32_t)__bfloat16_as_ushort(__float2bfloat16(b - __bfloat162float(h1))) << 16);
    return (uint32_t)__bfloat16_as_ushort(h0) | ((uint32_t)__bfloat16_as_ushort(h1) << 16);
}

// img [cam][512][px] f32 -> [cam][px][512] bf16 hi/lo
__global__ __launch_bounds__(256) void prep_img_kernel(const float* __restrict__ img)
{
    __shared__ float st[64][129];
    const int px0 = blockIdx.x * 128, cg = blockIdx.y, cam = blockIdx.z;
    const int tid = threadIdx.x;
    for (int i = tid; i < 64*128; i += 256) {
        const int c = i >> 7, p = i & 127;
        st[c][p] = img[((size_t)cam*512 + cg*64 + c)*NPIX + px0 + p];
    }
    __syncthreads();
    for (int i = tid; i < 128*16; i += 256) {
        const int p = i >> 4, c4 = (i & 15) * 4;
        uint2 hp, lp;
        hp.x = pack_hi(st[c4][p],   st[c4+1][p], lp.x);
        hp.y = pack_hi(st[c4+2][p], st[c4+3][p], lp.y);
        const size_t o = ((size_t)(cam*NPIX + px0 + p))*512 + cg*64 + c4;
        *(uint2*)&g_imgh[o] = hp;
        *(uint2*)&g_imgl[o] = lp;
    }
}

// weight transform, coalesced reads
template<int CIN>
__global__ __launch_bounds__(256) void wtrans2_kernel(const float* __restrict__ w, int htBase)
{
    constexpr int OCG = (CIN == 512) ? 4 : 8;
    constexpr int PER_OC = CIN * 9;
    constexpr int CIG = CIN / 64;
    extern __shared__ float s[];
    const int ocbase = blockIdx.x * OCG;
    const int layer  = blockIdx.y;
    const int tid = threadIdx.x;
    const int htB = htBase + layer * (CIG * 18);

    const float4* src = (const float4*)(w + (size_t)layer*256*PER_OC + (size_t)ocbase*PER_OC);
    for (int i = tid; i < OCG*PER_OC/4; i += 256) ((float4*)s)[i] = src[i];
    __syncthreads();

    const int half = ocbase >> 7;
    for (int t = tid; t < OCG*PER_OC/2; t += 256) {
        const int ci2 = t & 31, rowidx = t >> 5;
        const int oc_l = rowidx / (CIG*9);
        const int r2 = rowidx - oc_l*(CIG*9);
        const int cig = r2 / 9, tap = r2 - cig*9;
        const int ci = ci2*2;
        const float w0 = s[oc_l*PER_OC + (cig*64 + ci)*9 + tap];
        const float w1 = s[oc_l*PER_OC + (cig*64 + ci + 1)*9 + tap];
        uint32_t lo;
        const uint32_t hi = pack_hi(w0, w1, lo);
        const int ocl = (ocbase + oc_l) & 127;
        const int ht = htB + (tap*CIG + cig)*2 + half;
        const size_t off = (size_t)ht*16384 + SW128((uint32_t)(ocl*128 + ci*2));
        *(uint32_t*)((char*)g_Wh + off) = hi;
        *(uint32_t*)((char*)g_Wl + off) = lo;
    }
}

// depth weights [112][256] -> 4 tiles (128x64)
__global__ __launch_bounds__(256) void dtrans_kernel(const float* __restrict__ dw)
{
    const int t = blockIdx.x*256 + threadIdx.x;
    if (t >= 4*128*32) return;
    const int ci2 = t & 31, r = (t >> 5) & 127, c = t >> 12;
    const int ci = ci2*2;
    float w0 = 0.f, w1 = 0.f;
    if (r < DBINS) { w0 = dw[r*256 + c*64 + ci]; w1 = dw[r*256 + c*64 + ci + 1]; }
    uint32_t lo;
    const uint32_t hi = pack_hi(w0, w1, lo);
    const size_t off = (size_t)(WHT + c)*16384 + SW128((uint32_t)(r*128 + ci*2));
    *(uint32_t*)((char*)g_Wh + off) = hi;
    *(uint32_t*)((char*)g_Wl + off) = lo;
}

__global__ void gate_kernel(const float* __restrict__ intr,
                            const float* __restrict__ w1, const float* __restrict__ b1,
                            const float* __restrict__ w2, const float* __restrict__ b2,
                            const float* __restrict__ rw, const float* __restrict__ rb,
                            const float* __restrict__ ew, const float* __restrict__ eb,
                            float* __restrict__ gate)
{
    int cam = blockIdx.x, tid = threadIdx.x;
    __shared__ float sp_s, h[256], h2[256], t[256];
    if (tid == 0) {
        double A[4][8];
        for (int r = 0; r < 4; r++) {
            for (int c = 0; c < 4; c++) A[r][c] = (double)intr[cam*16 + r*4 + c];
            for (int c = 0; c < 4; c++) A[r][4+c] = (r == c) ? 1.0 : 0.0;
        }
        for (int col = 0; col < 4; col++) {
            int piv = col; double best = fabs(A[col][col]);
            for (int r = col+1; r < 4; r++)
                if (fabs(A[r][col]) > best) { best = fabs(A[r][col]); piv = r; }
            if (piv != col)
                for (int c = 0; c < 8; c++) { double tmp = A[col][c]; A[col][c] = A[piv][c]; A[piv][c] = tmp; }
            double d = A[col][col];
            for (int c = 0; c < 8; c++) A[col][c] /= d;
            for (int r = 0; r < 4; r++) if (r != col) {
                double f = A[r][col];
                for (int c = 0; c < 8; c++) A[r][c] -= f * A[col][c];
            }
        }
        sp_s = (float)(1000.0 * sqrt(A[0][4]*A[0][4] + A[1][5]*A[1][5]));
    }
    __syncthreads();
    float sp = sp_s;
    h[tid] = fmaxf(sp * w1[tid] + b1[tid], 0.f);
    __syncthreads();
    float s = b2[tid];
    for (int k = 0; k < 256; k++) s += h[k] * w2[k*256 + tid];
    h2[tid] = s;
    __syncthreads();
    s = rb[tid];
    for (int c = 0; c < 256; c++) s += rw[tid*256 + c] * h2[c];
    t[tid] = fmaxf(s, 0.f);
    __syncthreads();
    s = eb[tid];
    for (int c = 0; c < 256; c++) s += ew[tid*256 + c] * t[c];
    gate[cam*256 + tid] = 1.f / (1.f + __expf(-s));
}

// HMMA conv: 128px x 256oc, 16 warps, warp tile 32x64. Grid (22,1,6).
#define BUF 98304
#define CONV_SMEM (4096 + 2*BUF)
template<int CIN, int MODE>
__global__ void __launch_bounds__(512, 1)
conv_kernel(const __nv_bfloat16* __restrict__ inh, const __nv_bfloat16* __restrict__ inl,
            int aoff,
            const float* __restrict__ scale, const float* __restrict__ bias,
            const float* __restrict__ gate,  const float* res,
            float* outf, __nv_bfloat16* __restrict__ outh, __nv_bfloat16* __restrict__ outl)
{
    constexpr int CIG = CIN / 64, NCH = 9 * CIG;
    extern __shared__ __align__(1024) char smem[];
    float* s_sc = (float*)smem;
    float* s_bi = (float*)(smem + 1024);
    float* s_gt = (float*)(smem + 2048);
    const uint32_t sb0 = smem_u32(smem) + 4096;

    const int pxt = blockIdx.x, cam = blockIdx.z;
    const int tid = threadIdx.x, wid = tid >> 5, lane = tid & 31;
    const int wm = wid & 3, wn = wid >> 2;
    const int g = lane >> 2, tig = lane & 3;

    if (tid < 256) {
        s_sc[tid] = scale[tid];
        s_bi[tid] = bias [tid];
        s_gt[tid] = (MODE == 0) ? gate[cam*256 + tid] : 0.f;
    }

    float acc[2][8][4];
    #pragma unroll
    for (int a = 0; a < 2; a++)
        #pragma unroll
        for (int b = 0; b < 8; b++)
            #pragma unroll
            for (int c = 0; c < 4; c++) acc[a][b][c] = 0.f;

    const int arow = wm*32 + (lane & 15);
    const int ak16 = (lane >> 4) << 4;
    const int brow = wn*64 + (lane & 7) + ((lane >> 4) << 3);
    const int bk16 = ((lane >> 3) & 1) << 4;

    auto stage = [&](int j, int b) {
        const uint32_t dA = sb0 + b*BUF, dB = dA + 32768;
        const char* sH = (const char*)g_Wh + (size_t)(aoff + j*2) * 16384;
        const char* sL = (const char*)g_Wl + (size_t)(aoff + j*2) * 16384;
        #pragma unroll
        for (int t = 0; t < 4; t++) {
            const uint32_t o = (tid + 512*t) * 16;
            cpa16(dB + o,         sH + o, 16);
            cpa16(dB + 32768 + o, sL + o, 16);
        }
        const int tap = j / CIG, cig = j - tap*CIG;
        const int dh = tap/3 - 1, dw = tap%3 - 1;
        #pragma unroll
        for (int t = 0; t < 2; t++) {
            const int u = tid + 512*t;
            const int px = u >> 3, q = u & 7;
            const int p = pxt*128 + px;
            const int h = p/88 + dh, w = p - (p/88)*88 + dw;
            const bool ok = ((unsigned)h < 32u) & ((unsigned)w < 88u);
            const size_t s0 = ok ? (((size_t)(cam*NPIX + h*88 + w))*CIN + cig*64 + q*8) : 0;
            const int sz = ok ? 16 : 0;
            const uint32_t sw = SW128((uint32_t)(px*128 + q*16));
            cpa16(dA + sw,         inh + s0, sz);
            cpa16(dA + 16384 + sw, inl + s0, sz);
        }
        CPA_COMMIT();
    };

    stage(0, 0);
    #pragma unroll 1
    for (int j = 0; j < NCH; j++) {
        const int b = j & 1;
        CPA_WAIT0();
        __syncthreads();
        if (j + 1 < NCH) stage(j + 1, 1 - b);

        const uint32_t sbA = sb0 + b*BUF, sbB = sbA + 32768;
        #pragma unroll
        for (int ks = 0; ks < 4; ks++) {
            uint32_t ah[2][4], al[2][4];
            #pragma unroll
            for (int mt = 0; mt < 2; mt++) {
                const uint32_t off = (uint32_t)((arow + mt*16)*128 + ks*32) + ak16;
                LDM4(ah[mt][0],ah[mt][1],ah[mt][2],ah[mt][3], sbA + SW128(off));
                LDM4(al[mt][0],al[mt][1],al[mt][2],al[mt][3], sbA + 16384 + SW128(off));
            }
            #pragma unroll
            for (int np = 0; np < 4; np++) {
                uint32_t bh[4], bl[4];
                const uint32_t boff = (uint32_t)((brow + np*16)*128 + ks*32) + bk16;
                LDM4(bh[0],bh[1],bh[2],bh[3], sbB + SW128(boff));
                LDM4(bl[0],bl[1],bl[2],bl[3], sbB + 32768 + SW128(boff));
                #pragma unroll
                for (int mt = 0; mt < 2; mt++) {
                    MMA(acc[mt][np*2],   ah[mt], bh[0], bh[1]);
                    MMA(acc[mt][np*2+1], ah[mt], bh[2], bh[3]);
                    MMA(acc[mt][np*2],   ah[mt], bl[0], bl[1]);
                    MMA(acc[mt][np*2+1], ah[mt], bl[2], bl[3]);
                    MMA(acc[mt][np*2],   al[mt], bh[0], bh[1]);
                    MMA(acc[mt][np*2+1], al[mt], bh[2], bh[3]);
                }
            }
        }
    }

    const int pxb = pxt*128 + wm*32;
    #pragma unroll
    for (int mt = 0; mt < 2; mt++)
        #pragma unroll
        for (int nt = 0; nt < 8; nt++) {
            const int ocl = wn*64 + nt*8 + 2*tig;
            const float2 sc = *(float2*)&s_sc[ocl];
            const float2 bi = *(float2*)&s_bi[ocl];
            #pragma unroll
            for (int r = 0; r < 2; r++) {
                const int px = pxb + mt*16 + g + r*8;
                float vx = acc[mt][nt][r*2]   * sc.x + bi.x;
                float vy = acc[mt][nt][r*2+1] * sc.y + bi.y;
                const size_t base = (size_t)(cam*NPIX + px)*256 + ocl;
                if (MODE == 0) {
                    const float2 gt = *(float2*)&s_gt[ocl];
                    vx = fmaxf(vx, 0.f)*gt.x; vy = fmaxf(vy, 0.f)*gt.y;
                } else if (MODE == 1) {
                    vx = fmaxf(vx, 0.f); vy = fmaxf(vy, 0.f);
                } else {
                    const float2 r0 = *(const float2*)&res[base];
                    vx = fmaxf(vx + r0.x, 0.f); vy = fmaxf(vy + r0.y, 0.f);
                }
                if (MODE == 0 || MODE == 2)
                    *(float2*)&outf[base] = make_float2(vx, vy);
                uint32_t lo;
                const uint32_t hi = pack_hi(vx, vy, lo);
                *(uint32_t*)&outh[base] = hi;
                *(uint32_t*)&outl[base] = lo;
            }
        }
}

// depth logits via HMMA + fused softmax + coalesced writes. Grid (22,1,6), 256 thr.
#define LBUF 65536
#define LG_SMEM (1024 + 2*LBUF)
__global__ void __launch_bounds__(256, 1)
logit_softmax_kernel(const __nv_bfloat16* __restrict__ xh, const __nv_bfloat16* __restrict__ xl,
                     const float* __restrict__ bias, float* __restrict__ dp)
{
    extern __shared__ __align__(1024) char smem[];
    float* s_bi = (float*)smem;
    const uint32_t sb0 = smem_u32(smem) + 1024;
    float* slog = (float*)(smem + 1024);            // [128][132]
    float* spk  = slog + 128*132;                   // [128][112] packed probs

    const int pxt = blockIdx.x, cam = blockIdx.z;
    const int tid = threadIdx.x, wid = tid >> 5, lane = tid & 31;
    const int wm = wid & 3, wn = wid >> 2;
    const int g = lane >> 2, tig = lane & 3;
    const int campix0 = cam*NPIX + pxt*128;

    if (tid < 128) s_bi[tid] = (tid < DBINS) ? bias[tid] : 0.f;

    float acc[2][8][4];
    #pragma unroll
    for (int a = 0; a < 2; a++)
        #pragma unroll
        for (int b = 0; b < 8; b++)
            #pragma unroll
            for (int c = 0; c < 4; c++) acc[a][b][c] = 0.f;

    const int arow = wm*32 + (lane & 15);
    const int ak16 = (lane >> 4) << 4;
    const int brow = wn*64 + (lane & 7) + ((lane >> 4) << 3);
    const int bk16 = ((lane >> 3) & 1) << 4;

    auto stage = [&](int c, int b) {
        const uint32_t dA = sb0 + b*LBUF, dB = dA + 32768;
        const char* sH = (const char*)g_Wh + (size_t)(WHT + c)*16384;
        const char* sL = (const char*)g_Wl + (size_t)(WHT + c)*16384;
        #pragma unroll
        for (int t = 0; t < 4; t++) {
            const uint32_t o = (tid + 256*t) * 16;
            cpa16(dB + o,         sH + o, 16);
            cpa16(dB + 16384 + o, sL + o, 16);
        }
        #pragma unroll
        for (int t = 0; t < 4; t++) {
            const int u = tid + 256*t;
            const int px = u >> 3, q = u & 7;
            const size_t s0 = (size_t)(campix0 + px)*256 + c*64 + q*8;
            const uint32_t sw = SW128((uint32_t)(px*128 + q*16));
            cpa16(dA + sw,         xh + s0, 16);
            cpa16(dA + 16384 + sw, xl + s0, 16);
        }
        CPA_COMMIT();
    };

    stage(0, 0);
    #pragma unroll 1
    for (int c = 0; c < 4; c++) {
        const int b = c & 1;
        CPA_WAIT0();
        __syncthreads();
        if (c + 1 < 4) stage(c + 1, 1 - b);

        const uint32_t sbA = sb0 + b*LBUF, sbB = sbA + 32768;
        #pragma unroll
        for (int ks = 0; ks < 4; ks++) {
            uint32_t ah[2][4], al[2][4];
            #pragma unroll
            for (int mt = 0; mt < 2; mt++) {
                const uint32_t off = (uint32_t)((arow + mt*16)*128 + ks*32) + ak16;
                LDM4(ah[mt][0],ah[mt][1],ah[mt][2],ah[mt][3], sbA + SW128(off));
                LDM4(al[mt][0],al[mt][1],al[mt][2],al[mt][3], sbA + 16384 + SW128(off));
            }
            #pragma unroll
            for (int np = 0; np < 4; np++) {
                uint32_t bh[4], bl[4];
                const uint32_t boff = (uint32_t)((brow + np*16)*128 + ks*32) + bk16;
                LDM4(bh[0],bh[1],bh[2],bh[3], sbB + SW128(boff));
                LDM4(bl[0],bl[1],bl[2],bl[3], sbB + 16384 + SW128(boff));
                #pragma unroll
                for (int mt = 0; mt < 2; mt++) {
                    MMA(acc[mt][np*2],   ah[mt], bh[0], bh[1]);
                    MMA(acc[mt][np*2+1], ah[mt], bh[2], bh[3]);
                    MMA(acc[mt][np*2],   ah[mt], bl[0], bl[1]);
                    MMA(acc[mt][np*2+1], ah[mt], bl[2], bl[3]);
                    MMA(acc[mt][np*2],   al[mt], bh[0], bh[1]);
                    MMA(acc[mt][np*2+1], al[mt], bh[2], bh[3]);
                }
            }
        }
    }
    __syncthreads();

    #pragma unroll
    for (int mt = 0; mt < 2; mt++)
        #pragma unroll
        for (int nt = 0; nt < 8; nt++) {
            const int n = wn*64 + nt*8 + 2*tig;
            #pragma unroll
            for (int r = 0; r < 2; r++) {
                const int px = wm*32 + mt*16 + g + r*8;
                *(float2*)&slog[px*132 + n] =
                    make_float2(acc[mt][nt][r*2] + s_bi[n], acc[mt][nt][r*2+1] + s_bi[n+1]);
            }
        }
    __syncthreads();

    // softmax: 2 threads per px -> packed smem
    {
        const int px = tid >> 1, part = tid & 1;
        const float* row = &slog[px*132 + part*64];
        const int cnt = part ? 48 : 64;
        float m = -1e30f;
        for (int i = 0; i < cnt; i++) m = fmaxf(m, row[i]);
        m = fmaxf(m, __shfl_xor_sync(0xffffffffu, m, 1));
        float s = 0.f;
        for (int i = 0; i < cnt; i++) s += __expf(row[i] - m);
        s += __shfl_xor_sync(0xffffffffu, s, 1);
        const float inv = 1.f / s;
        float* prow = &spk[px*112 + part*64];
        for (int i = 0; i < cnt; i++) prow[i] = __expf(row[i] - m) * inv;
    }
    __syncthreads();

    // coalesced copy: 128*112 floats contiguous in dp
    float4* dst = (float4*)&dp[(size_t)campix0 * DBINS];
    const float4* srcp = (const float4*)spk;
    for (int i = tid; i < 128*112/4; i += 256) dst[i] = srcp[i];
}

// trilinear sample; grid coords preloaded, cam loop unrolled for MLP
__global__ __launch_bounds__(256)
void sample_kernel(const float* __restrict__ grid, const float* __restrict__ dp,
                   float* __restrict__ out)
{
    const int v = blockIdx.x * blockDim.x + threadIdx.x;
    if (v >= NVOX) return;

    float gx[NCAM], gy[NCAM], gz[NCAM];
    #pragma unroll
    for (int cam = 0; cam < NCAM; cam++) {
        const float* g = grid + ((size_t)cam * NVOX + v) * 3;
        gx[cam] = g[0]; gy[cam] = g[1]; gz[cam] = g[2];
    }

    float agg = 0.f, mask = 0.f;
    #pragma unroll
    for (int cam = 0; cam < NCAM; cam++) {
        const float ix = ((gx[cam] + 1.f) * 88.f  - 1.f) * 0.5f;
        const float iy = ((gy[cam] + 1.f) * 32.f  - 1.f) * 0.5f;
        const float iz = ((gz[cam] + 1.f) * 112.f - 1.f) * 0.5f;
        const float fx0 = floorf(ix), fy0 = floorf(iy), fz0 = floorf(iz);
        const float fx = ix - fx0, fy = iy - fy0, fz = iz - fz0;
        const int x0 = (int)fx0, y0 = (int)fy0, z0 = (int)fz0;
        const float* dc = dp + (size_t)cam * NPIX * DBINS;
        #pragma unroll
        for (int dy = 0; dy < 2; dy++)
            #pragma unroll
            for (int dx = 0; dx < 2; dx++) {
                const int xi = x0 + dx, yi = y0 + dy;
                if ((unsigned)xi < 88u && (unsigned)yi < 32u) {
                    const float wxy = (dx ? fx : 1.f-fx) * (dy ? fy : 1.f-fy);
                    const float* dr = dc + (size_t)(yi*88 + xi) * DBINS;
                    #pragma unroll
                    for (int dz = 0; dz < 2; dz++) {
                        const int zi = z0 + dz;
                        const float wv = wxy * (dz ? fz : 1.f-fz);
                        if ((unsigned)zi < 112u) { agg += wv * dr[zi]; mask += wv; }
                    }
                }
            }
    }
    out[v] = (mask > 0.f) ? (agg / mask) : agg;
}

extern "C" void kernel_launch(void* const* d_in, const int* in_sizes, int n_in,
                              void* d_out, int out_size)
{
    const float* img    = (const float*)d_in[0];
    const float* intr   = (const float*)d_in[1];
    const float* grid   = (const float*)d_in[2];
    const float* red_w  = (const float*)d_in[3];
    const float* red_s  = (const float*)d_in[4];
    const float* red_b  = (const float*)d_in[5];
    const float* mlp_w1 = (const float*)d_in[6];
    const float* mlp_b1 = (const float*)d_in[7];
    const float* mlp_w2 = (const float*)d_in[8];
    const float* mlp_b2 = (const float*)d_in[9];
    const float* se_rw  = (const float*)d_in[10];
    const float* se_rb  = (const float*)d_in[11];
    const float* se_ew  = (const float*)d_in[12];
    const float* se_eb  = (const float*)d_in[13];
    const float* bb_w   = (const float*)d_in[14];
    const float* bb_s   = (const float*)d_in[15];
    const float* bb_b   = (const float*)d_in[16];
    const float* dp_w   = (const float*)d_in[17];
    const float* dp_b   = (const float*)d_in[18];

    float *pxf, *pdp, *pg;
    __nv_bfloat16 *pih, *pil, *pxh, *pxl, *pyh, *pyl;
    cudaGetSymbolAddress((void**)&pxf, g_xf);
    cudaGetSymbolAddress((void**)&pdp, g_dp);
    cudaGetSymbolAddress((void**)&pg,  g_gate);
    cudaGetSymbolAddress((void**)&pih, g_imgh);
    cudaGetSymbolAddress((void**)&pil, g_imgl);
    cudaGetSymbolAddress((void**)&pxh, g_xh);
    cudaGetSymbolAddress((void**)&pxl, g_xl);
    cudaGetSymbolAddress((void**)&pyh, g_yh);
    cudaGetSymbolAddress((void**)&pyl, g_yl);

    cudaFuncSetAttribute(conv_kernel<512,0>, cudaFuncAttributeMaxDynamicSharedMemorySize, CONV_SMEM);
    cudaFuncSetAttribute(conv_kernel<256,1>, cudaFuncAttributeMaxDynamicSharedMemorySize, CONV_SMEM);
    cudaFuncSetAttribute(conv_kernel<256,2>, cudaFuncAttributeMaxDynamicSharedMemorySize, CONV_SMEM);
    cudaFuncSetAttribute(conv_kernel<256,4>, cudaFuncAttributeMaxDynamicSharedMemorySize, CONV_SMEM);
    cudaFuncSetAttribute(logit_softmax_kernel, cudaFuncAttributeMaxDynamicSharedMemorySize, LG_SMEM);
    cudaFuncSetAttribute(wtrans2_kernel<512>, cudaFuncAttributeMaxDynamicSharedMemorySize, 73728);
    cudaFuncSetAttribute(wtrans2_kernel<256>, cudaFuncAttributeMaxDynamicSharedMemorySize, 73728);

    gate_kernel<<<NCAM, 256>>>(intr, mlp_w1, mlp_b1, mlp_w2, mlp_b2,
                               se_rw, se_rb, se_ew, se_eb, pg);
    prep_img_kernel<<<dim3(22, 8, NCAM), 256>>>(img);
    wtrans2_kernel<512><<<dim3(64, 1), 256, 73728>>>(red_w, 0);
    wtrans2_kernel<256><<<dim3(32, 6), 256, 73728>>>(bb_w, 144);
    dtrans_kernel<<<64, 256>>>(dp_w);

    dim3 cg(22, 1, NCAM);
    conv_kernel<512,0><<<cg, 512, CONV_SMEM>>>(pih, pil, 0, red_s, red_b, pg,
                                               nullptr, pxf, pxh, pxl);
    for (int i = 0; i < 3; i++) {
        conv_kernel<256,1><<<cg, 512, CONV_SMEM>>>(pxh, pxl, 144 + (2*i)*72,
            bb_s + (2*i)*MID, bb_b + (2*i)*MID, nullptr, nullptr, nullptr, pyh, pyl);
        if (i < 2)
            conv_kernel<256,2><<<cg, 512, CONV_SMEM>>>(pyh, pyl, 144 + (2*i+1)*72,
                bb_s + (2*i+1)*MID, bb_b + (2*i+1)*MID, nullptr, pxf, pxf, pxh, pxl);
        else
            conv_kernel<256,4><<<cg, 512, CONV_SMEM>>>(pyh, pyl, 144 + (2*i+1)*72,
                bb_s + (2*i+1)*MID, bb_b + (2*i+1)*MID, nullptr, pxf, nullptr, pxh, pxl);
    }
    logit_softmax_kernel<<<cg, 256, LG_SMEM>>>(pxh, pxl, dp_b, pdp);
    sample_kernel<<<(NVOX + 255)/256, 256>>>(grid, pdp, (float*)d_out);
}

// round 15
// speedup vs baseline: 1.0093x; 1.0093x over previous
#include <cuda_runtime.h>
#include <cuda_bf16.h>
#include <math.h>
#include <stdint.h>

#define NCAM 6
#define MID 256
#define DBINS 112
#define HH 32
#define WW 88
#define NPIX 2816
#define NVOX (128*128*16)
#define WHT 576                 // conv tiles; depth tiles at 576..579

__device__ __align__(1024) float g_dp [NCAM*NPIX*DBINS];
__device__ __align__(1024) float g_gate[NCAM*MID];
__device__ __align__(1024) __nv_bfloat16 g_imgh[NCAM*NPIX*512];
__device__ __align__(1024) __nv_bfloat16 g_imgl[NCAM*NPIX*512];
__device__ __align__(1024) __nv_bfloat16 g_xh[NCAM*NPIX*MID];
__device__ __align__(1024) __nv_bfloat16 g_xl[NCAM*NPIX*MID];
__device__ __align__(1024) __nv_bfloat16 g_yh[NCAM*NPIX*MID];
__device__ __align__(1024) __nv_bfloat16 g_yl[NCAM*NPIX*MID];
__device__ __align__(1024) __nv_bfloat16 g_Wh[(WHT+4)*128*64];
__device__ __align__(1024) __nv_bfloat16 g_Wl[(WHT+4)*128*64];

__device__ __forceinline__ uint32_t smem_u32(const void* p) {
    uint32_t a;
    asm("{ .reg .u64 t; cvta.to.shared.u64 t, %1; cvt.u32.u64 %0, t; }" : "=r"(a) : "l"(p));
    return a;
}
#define SW128(o) ((o) ^ (((o) >> 3) & 0x70))
#define LDM4(r0,r1,r2,r3,addr) \
    asm volatile("ldmatrix.sync.aligned.m8n8.x4.shared.b16 {%0,%1,%2,%3}, [%4];" \
        : "=r"(r0),"=r"(r1),"=r"(r2),"=r"(r3) : "r"(addr))
#define MMA(d,a,b0,b1) \
    asm volatile("mma.sync.aligned.m16n8k16.row.col.f32.bf16.bf16.f32 " \
        "{%0,%1,%2,%3},{%4,%5,%6,%7},{%8,%9},{%0,%1,%2,%3};" \
        : "+f"((d)[0]),"+f"((d)[1]),"+f"((d)[2]),"+f"((d)[3]) \
        : "r"((a)[0]),"r"((a)[1]),"r"((a)[2]),"r"((a)[3]),"r"(b0),"r"(b1))
__device__ __forceinline__ void cpa16(uint32_t dst, const void* src, int sz) {
    asm volatile("cp.async.cg.shared.global [%0], [%1], 16, %2;" :: "r"(dst), "l"(src), "r"(sz) : "memory");
}
#define CPA_COMMIT() asm volatile("cp.async.commit_group;" ::: "memory")
#define CPA_WAIT0()  asm volatile("cp.async.wait_group 0;" ::: "memory")

__device__ __forceinline__ uint32_t pack_hi(float a, float b, uint32_t &lo) {
    const __nv_bfloat16 h0 = __float2bfloat16(a), h1 = __float2bfloat16(b);
    lo = (uint32_t)__bfloat16_as_ushort(__float2bfloat16(a - __bfloat162float(h0)))
       | ((uint32_t)__bfloat16_as_ushort(__float2bfloat16(b - __bfloat162float(h1))) << 16);
    return (uint32_t)__bfloat16_as_ushort(h0) | ((uint32_t)__bfloat16_as_ushort(h1) << 16);
}
__device__ __forceinline__ float bfu(uint32_t u) {
    return __bfloat162float(__ushort_as_bfloat16((unsigned short)u));
}

// img [cam][512][px] f32 -> [cam][px][512] bf16 hi/lo
__global__ __launch_bounds__(256) void prep_img_kernel(const float* __restrict__ img)
{
    __shared__ float st[64][129];
    const int px0 = blockIdx.x * 128, cg = blockIdx.y, cam = blockIdx.z;
    const int tid = threadIdx.x;
    for (int i = tid; i < 64*128; i += 256) {
        const int c = i >> 7, p = i & 127;
        st[c][p] = img[((size_t)cam*512 + cg*64 + c)*NPIX + px0 + p];
    }
    __syncthreads();
    for (int i = tid; i < 128*16; i += 256) {
        const int p = i >> 4, c4 = (i & 15) * 4;
        uint2 hp, lp;
        hp.x = pack_hi(st[c4][p],   st[c4+1][p], lp.x);
        hp.y = pack_hi(st[c4+2][p], st[c4+3][p], lp.y);
        const size_t o = ((size_t)(cam*NPIX + px0 + p))*512 + cg*64 + c4;
        *(uint2*)&g_imgh[o] = hp;
        *(uint2*)&g_imgl[o] = lp;
    }
}

// weight transform, coalesced reads
template<int CIN>
__global__ __launch_bounds__(256) void wtrans2_kernel(const float* __restrict__ w, int htBase)
{
    constexpr int OCG = (CIN == 512) ? 4 : 8;
    constexpr int PER_OC = CIN * 9;
    constexpr int CIG = CIN / 64;
    extern __shared__ float s[];
    const int ocbase = blockIdx.x * OCG;
    const int layer  = blockIdx.y;
    const int tid = threadIdx.x;
    const int htB = htBase + layer * (CIG * 18);

    const float4* src = (const float4*)(w + (size_t)layer*256*PER_OC + (size_t)ocbase*PER_OC);
    for (int i = tid; i < OCG*PER_OC/4; i += 256) ((float4*)s)[i] = src[i];
    __syncthreads();

    const int half = ocbase >> 7;
    for (int t = tid; t < OCG*PER_OC/2; t += 256) {
        const int ci2 = t & 31, rowidx = t >> 5;
        const int oc_l = rowidx / (CIG*9);
        const int r2 = rowidx - oc_l*(CIG*9);
        const int cig = r2 / 9, tap = r2 - cig*9;
        const int ci = ci2*2;
        const float w0 = s[oc_l*PER_OC + (cig*64 + ci)*9 + tap];
        const float w1 = s[oc_l*PER_OC + (cig*64 + ci + 1)*9 + tap];
        uint32_t lo;
        const uint32_t hi = pack_hi(w0, w1, lo);
        const int ocl = (ocbase + oc_l) & 127;
        const int ht = htB + (tap*CIG + cig)*2 + half;
        const size_t off = (size_t)ht*16384 + SW128((uint32_t)(ocl*128 + ci*2));
        *(uint32_t*)((char*)g_Wh + off) = hi;
        *(uint32_t*)((char*)g_Wl + off) = lo;
    }
}

// depth weights [112][256] -> 4 tiles (128x64)
__global__ __launch_bounds__(256) void dtrans_kernel(const float* __restrict__ dw)
{
    const int t = blockIdx.x*256 + threadIdx.x;
    if (t >= 4*128*32) return;
    const int ci2 = t & 31, r = (t >> 5) & 127, c = t >> 12;
    const int ci = ci2*2;
    float w0 = 0.f, w1 = 0.f;
    if (r < DBINS) { w0 = dw[r*256 + c*64 + ci]; w1 = dw[r*256 + c*64 + ci + 1]; }
    uint32_t lo;
    const uint32_t hi = pack_hi(w0, w1, lo);
    const size_t off = (size_t)(WHT + c)*16384 + SW128((uint32_t)(r*128 + ci*2));
    *(uint32_t*)((char*)g_Wh + off) = hi;
    *(uint32_t*)((char*)g_Wl + off) = lo;
}

__global__ void gate_kernel(const float* __restrict__ intr,
                            const float* __restrict__ w1, const float* __restrict__ b1,
                            const float* __restrict__ w2, const float* __restrict__ b2,
                            const float* __restrict__ rw, const float* __restrict__ rb,
                            const float* __restrict__ ew, const float* __restrict__ eb,
                            float* __restrict__ gate)
{
    int cam = blockIdx.x, tid = threadIdx.x;
    __shared__ float sp_s, h[256], h2[256], t[256];
    if (tid == 0) {
        double A[4][8];
        for (int r = 0; r < 4; r++) {
            for (int c = 0; c < 4; c++) A[r][c] = (double)intr[cam*16 + r*4 + c];
            for (int c = 0; c < 4; c++) A[r][4+c] = (r == c) ? 1.0 : 0.0;
        }
        for (int col = 0; col < 4; col++) {
            int piv = col; double best = fabs(A[col][col]);
            for (int r = col+1; r < 4; r++)
                if (fabs(A[r][col]) > best) { best = fabs(A[r][col]); piv = r; }
            if (piv != col)
                for (int c = 0; c < 8; c++) { double tmp = A[col][c]; A[col][c] = A[piv][c]; A[piv][c] = tmp; }
            double d = A[col][col];
            for (int c = 0; c < 8; c++) A[col][c] /= d;
            for (int r = 0; r < 4; r++) if (r != col) {
                double f = A[r][col];
                for (int c = 0; c < 8; c++) A[r][c] -= f * A[col][c];
            }
        }
        sp_s = (float)(1000.0 * sqrt(A[0][4]*A[0][4] + A[1][5]*A[1][5]));
    }
    __syncthreads();
    float sp = sp_s;
    h[tid] = fmaxf(sp * w1[tid] + b1[tid], 0.f);
    __syncthreads();
    float s = b2[tid];
    for (int k = 0; k < 256; k++) s += h[k] * w2[k*256 + tid];
    h2[tid] = s;
    __syncthreads();
    s = rb[tid];
    for (int c = 0; c < 256; c++) s += rw[tid*256 + c] * h2[c];
    t[tid] = fmaxf(s, 0.f);
    __syncthreads();
    s = eb[tid];
    for (int c = 0; c < 256; c++) s += ew[tid*256 + c] * t[c];
    gate[cam*256 + tid] = 1.f / (1.f + __expf(-s));
}

// HMMA conv: 128px x 256oc, 16 warps, warp tile 32x64. Grid (22,1,6).
// Staging of chunk j+1 interleaved into ks loop of chunk j (3 parts of 4 cp.async).
// MODE 0: relu*gate; 1: relu; 2: relu(res+), residual from bf16 splits. All write splits.
#define BUF 98304
#define CONV_SMEM (4096 + 2*BUF)
template<int CIN, int MODE>
__global__ void __launch_bounds__(512, 1)
conv_kernel(const __nv_bfloat16* __restrict__ inh, const __nv_bfloat16* __restrict__ inl,
            int aoff,
            const float* __restrict__ scale, const float* __restrict__ bias,
            const float* __restrict__ gate,
            const __nv_bfloat16* __restrict__ resh, const __nv_bfloat16* __restrict__ resl,
            __nv_bfloat16* __restrict__ outh, __nv_bfloat16* __restrict__ outl)
{
    constexpr int CIG = CIN / 64, NCH = 9 * CIG;
    extern __shared__ __align__(1024) char smem[];
    float* s_sc = (float*)smem;
    float* s_bi = (float*)(smem + 1024);
    float* s_gt = (float*)(smem + 2048);
    const uint32_t sb0 = smem_u32(smem) + 4096;

    const int pxt = blockIdx.x, cam = blockIdx.z;
    const int tid = threadIdx.x, wid = tid >> 5, lane = tid & 31;
    const int wm = wid & 3, wn = wid >> 2;
    const int g = lane >> 2, tig = lane & 3;

    if (tid < 256) {
        s_sc[tid] = scale[tid];
        s_bi[tid] = bias [tid];
        s_gt[tid] = (MODE == 0) ? gate[cam*256 + tid] : 0.f;
    }

    float acc[2][8][4];
    #pragma unroll
    for (int a = 0; a < 2; a++)
        #pragma unroll
        for (int b = 0; b < 8; b++)
            #pragma unroll
            for (int c = 0; c < 4; c++) acc[a][b][c] = 0.f;

    const int arow = wm*32 + (lane & 15);
    const int ak16 = (lane >> 4) << 4;
    const int brow = wn*64 + (lane & 7) + ((lane >> 4) << 3);
    const int bk16 = ((lane >> 3) & 1) << 4;

    // part 0: B rows t=0,1 ; part 1: B rows t=2,3 ; part 2: A (4 cp.async)
    auto stage_part = [&](int j, int b, int part) {
        const uint32_t dA = sb0 + b*BUF, dB = dA + 32768;
        if (part < 2) {
            const char* sH = (const char*)g_Wh + (size_t)(aoff + j*2) * 16384;
            const char* sL = (const char*)g_Wl + (size_t)(aoff + j*2) * 16384;
            #pragma unroll
            for (int t = 0; t < 2; t++) {
                const uint32_t o = (tid + 512*(part*2 + t)) * 16;
                cpa16(dB + o,         sH + o, 16);
                cpa16(dB + 32768 + o, sL + o, 16);
            }
        } else {
            const int tap = j / CIG, cig = j - tap*CIG;
            const int dh = tap/3 - 1, dw = tap%3 - 1;
            #pragma unroll
            for (int t = 0; t < 2; t++) {
                const int u = tid + 512*t;
                const int px = u >> 3, q = u & 7;
                const int p = pxt*128 + px;
                const int h = p/88 + dh, w = p - (p/88)*88 + dw;
                const bool ok = ((unsigned)h < 32u) & ((unsigned)w < 88u);
                const size_t s0 = ok ? (((size_t)(cam*NPIX + h*88 + w))*CIN + cig*64 + q*8) : 0;
                const int sz = ok ? 16 : 0;
                const uint32_t sw = SW128((uint32_t)(px*128 + q*16));
                cpa16(dA + sw,         inh + s0, sz);
                cpa16(dA + 16384 + sw, inl + s0, sz);
            }
        }
    };

    stage_part(0, 0, 0); stage_part(0, 0, 1); stage_part(0, 0, 2);
    CPA_COMMIT();

    #pragma unroll 1
    for (int j = 0; j < NCH; j++) {
        const int b = j & 1;
        CPA_WAIT0();
        __syncthreads();
        const bool more = (j + 1 < NCH);

        const uint32_t sbA = sb0 + b*BUF, sbB = sbA + 32768;
        #pragma unroll
        for (int ks = 0; ks < 4; ks++) {
            uint32_t ah[2][4], al[2][4];
            #pragma unroll
            for (int mt = 0; mt < 2; mt++) {
                const uint32_t off = (uint32_t)((arow + mt*16)*128 + ks*32) + ak16;
                LDM4(ah[mt][0],ah[mt][1],ah[mt][2],ah[mt][3], sbA + SW128(off));
                LDM4(al[mt][0],al[mt][1],al[mt][2],al[mt][3], sbA + 16384 + SW128(off));
            }
            // interleaved staging of chunk j+1 (issue slots fill MMA bubbles)
            if (more && ks < 3) {
                stage_part(j + 1, 1 - b, ks);
                if (ks == 2) CPA_COMMIT();
            }
            #pragma unroll
            for (int np = 0; np < 4; np++) {
                uint32_t bh[4], bl[4];
                const uint32_t boff = (uint32_t)((brow + np*16)*128 + ks*32) + bk16;
                LDM4(bh[0],bh[1],bh[2],bh[3], sbB + SW128(boff));
                LDM4(bl[0],bl[1],bl[2],bl[3], sbB + 32768 + SW128(boff));
                #pragma unroll
                for (int mt = 0; mt < 2; mt++) {
                    MMA(acc[mt][np*2],   ah[mt], bh[0], bh[1]);
                    MMA(acc[mt][np*2+1], ah[mt], bh[2], bh[3]);
                    MMA(acc[mt][np*2],   ah[mt], bl[0], bl[1]);
                    MMA(acc[mt][np*2+1], ah[mt], bl[2], bl[3]);
                    MMA(acc[mt][np*2],   al[mt], bh[0], bh[1]);
                    MMA(acc[mt][np*2+1], al[mt], bh[2], bh[3]);
                }
            }
        }
    }

    const int pxb = pxt*128 + wm*32;
    #pragma unroll
    for (int mt = 0; mt < 2; mt++)
        #pragma unroll
        for (int nt = 0; nt < 8; nt++) {
            const int ocl = wn*64 + nt*8 + 2*tig;
            const float2 sc = *(float2*)&s_sc[ocl];
            const float2 bi = *(float2*)&s_bi[ocl];
            #pragma unroll
            for (int r = 0; r < 2; r++) {
                const int px = pxb + mt*16 + g + r*8;
                float vx = acc[mt][nt][r*2]   * sc.x + bi.x;
                float vy = acc[mt][nt][r*2+1] * sc.y + bi.y;
                const size_t base = (size_t)(cam*NPIX + px)*256 + ocl;
                if (MODE == 0) {
                    const float2 gt = *(float2*)&s_gt[ocl];
                    vx = fmaxf(vx, 0.f)*gt.x; vy = fmaxf(vy, 0.f)*gt.y;
                } else if (MODE == 1) {
                    vx = fmaxf(vx, 0.f); vy = fmaxf(vy, 0.f);
                } else {
                    const uint32_t rh = *(const uint32_t*)&resh[base];
                    const uint32_t rl = *(const uint32_t*)&resl[base];
                    vx = fmaxf(vx + bfu(rh & 0xffffu) + bfu(rl & 0xffffu), 0.f);
                    vy = fmaxf(vy + bfu(rh >> 16)     + bfu(rl >> 16),     0.f);
                }
                uint32_t lo;
                const uint32_t hi = pack_hi(vx, vy, lo);
                *(uint32_t*)&outh[base] = hi;
                *(uint32_t*)&outl[base] = lo;
            }
        }
}

// depth logits via HMMA + fused softmax + coalesced writes. Grid (22,1,6), 256 thr.
#define LBUF 65536
#define LG_SMEM (1024 + 2*LBUF)
__global__ void __launch_bounds__(256, 1)
logit_softmax_kernel(const __nv_bfloat16* __restrict__ xh, const __nv_bfloat16* __restrict__ xl,
                     const float* __restrict__ bias, float* __restrict__ dp)
{
    extern __shared__ __align__(1024) char smem[];
    float* s_bi = (float*)smem;
    const uint32_t sb0 = smem_u32(smem) + 1024;
    float* slog = (float*)(smem + 1024);            // [128][132]
    float* spk  = slog + 128*132;                   // [128][112]

    const int pxt = blockIdx.x, cam = blockIdx.z;
    const int tid = threadIdx.x, wid = tid >> 5, lane = tid & 31;
    const int wm = wid & 3, wn = wid >> 2;
    const int g = lane >> 2, tig = lane & 3;
    const int campix0 = cam*NPIX + pxt*128;

    if (tid < 128) s_bi[tid] = (tid < DBINS) ? bias[tid] : 0.f;

    float acc[2][8][4];
    #pragma unroll
    for (int a = 0; a < 2; a++)
        #pragma unroll
        for (int b = 0; b < 8; b++)
            #pragma unroll
            for (int c = 0; c < 4; c++) acc[a][b][c] = 0.f;

    const int arow = wm*32 + (lane & 15);
    const int ak16 = (lane >> 4) << 4;
    const int brow = wn*64 + (lane & 7) + ((lane >> 4) << 3);
    const int bk16 = ((lane >> 3) & 1) << 4;

    auto stage = [&](int c, int b) {
        const uint32_t dA = sb0 + b*LBUF, dB = dA + 32768;
        const char* sH = (const char*)g_Wh + (size_t)(WHT + c)*16384;
        const char* sL = (const char*)g_Wl + (size_t)(WHT + c)*16384;
        #pragma unroll
        for (int t = 0; t < 4; t++) {
            const uint32_t o = (tid + 256*t) * 16;
            cpa16(dB + o,         sH + o, 16);
            cpa16(dB + 16384 + o, sL + o, 16);
        }
        #pragma unroll
        for (int t = 0; t < 4; t++) {
            const int u = tid + 256*t;
            const int px = u >> 3, q = u & 7;
            const size_t s0 = (size_t)(campix0 + px)*256 + c*64 + q*8;
            const uint32_t sw = SW128((uint32_t)(px*128 + q*16));
            cpa16(dA + sw,         xh + s0, 16);
            cpa16(dA + 16384 + sw, xl + s0, 16);
        }
        CPA_COMMIT();
    };

    stage(0, 0);
    #pragma unroll 1
    for (int c = 0; c < 4; c++) {
        const int b = c & 1;
        CPA_WAIT0();
        __syncthreads();
        if (c + 1 < 4) stage(c + 1, 1 - b);

        const uint32_t sbA = sb0 + b*LBUF, sbB = sbA + 32768;
        #pragma unroll
        for (int ks = 0; ks < 4; ks++) {
            uint32_t ah[2][4], al[2][4];
            #pragma unroll
            for (int mt = 0; mt < 2; mt++) {
                const uint32_t off = (uint32_t)((arow + mt*16)*128 + ks*32) + ak16;
                LDM4(ah[mt][0],ah[mt][1],ah[mt][2],ah[mt][3], sbA + SW128(off));
                LDM4(al[mt][0],al[mt][1],al[mt][2],al[mt][3], sbA + 16384 + SW128(off));
            }
            #pragma unroll
            for (int np = 0; np < 4; np++) {
                uint32_t bh[4], bl[4];
                const uint32_t boff = (uint32_t)((brow + np*16)*128 + ks*32) + bk16;
                LDM4(bh[0],bh[1],bh[2],bh[3], sbB + SW128(boff));
                LDM4(bl[0],bl[1],bl[2],bl[3], sbB + 16384 + SW128(boff));
                #pragma unroll
                for (int mt = 0; mt < 2; mt++) {
                    MMA(acc[mt][np*2],   ah[mt], bh[0], bh[1]);
                    MMA(acc[mt][np*2+1], ah[mt], bh[2], bh[3]);
                    MMA(acc[mt][np*2],   ah[mt], bl[0], bl[1]);
                    MMA(acc[mt][np*2+1], ah[mt], bl[2], bl[3]);
                    MMA(acc[mt][np*2],   al[mt], bh[0], bh[1]);
                    MMA(acc[mt][np*2+1], al[mt], bh[2], bh[3]);
                }
            }
        }
    }
    __syncthreads();

    #pragma unroll
    for (int mt = 0; mt < 2; mt++)
        #pragma unroll
        for (int nt = 0; nt < 8; nt++) {
            const int n = wn*64 + nt*8 + 2*tig;
            #pragma unroll
            for (int r = 0; r < 2; r++) {
                const int px = wm*32 + mt*16 + g + r*8;
                *(float2*)&slog[px*132 + n] =
                    make_float2(acc[mt][nt][r*2] + s_bi[n], acc[mt][nt][r*2+1] + s_bi[n+1]);
            }
        }
    __syncthreads();

    {
        const int px = tid >> 1, part = tid & 1;
        const float* row = &slog[px*132 + part*64];
        const int cnt = part ? 48 : 64;
        float m = -1e30f;
        for (int i = 0; i < cnt; i++) m = fmaxf(m, row[i]);
        m = fmaxf(m, __shfl_xor_sync(0xffffffffu, m, 1));
        float s = 0.f;
        for (int i = 0; i < cnt; i++) s += __expf(row[i] - m);
        s += __shfl_xor_sync(0xffffffffu, s, 1);
        const float inv = 1.f / s;
        float* prow = &spk[px*112 + part*64];
        for (int i = 0; i < cnt; i++) prow[i] = __expf(row[i] - m) * inv;
    }
    __syncthreads();

    float4* dst = (float4*)&dp[(size_t)campix0 * DBINS];
    const float4* srcp = (const float4*)spk;
    for (int i = tid; i < 128*112/4; i += 256) dst[i] = srcp[i];
}

// trilinear sample; grid coords preloaded, cam loop unrolled for MLP
__global__ __launch_bounds__(256)
void sample_kernel(const float* __restrict__ grid, const float* __restrict__ dp,
                   float* __restrict__ out)
{
    const int v = blockIdx.x * blockDim.x + threadIdx.x;
    if (v >= NVOX) return;

    float gx[NCAM], gy[NCAM], gz[NCAM];
    #pragma unroll
    for (int cam = 0; cam < NCAM; cam++) {
        const float* g = grid + ((size_t)cam * NVOX + v) * 3;
        gx[cam] = g[0]; gy[cam] = g[1]; gz[cam] = g[2];
    }

    float agg = 0.f, mask = 0.f;
    #pragma unroll
    for (int cam = 0; cam < NCAM; cam++) {
        const float ix = ((gx[cam] + 1.f) * 88.f  - 1.f) * 0.5f;
        const float iy = ((gy[cam] + 1.f) * 32.f  - 1.f) * 0.5f;
        const float iz = ((gz[cam] + 1.f) * 112.f - 1.f) * 0.5f;
        const float fx0 = floorf(ix), fy0 = floorf(iy), fz0 = floorf(iz);
        const float fx = ix - fx0, fy = iy - fy0, fz = iz - fz0;
        const int x0 = (int)fx0, y0 = (int)fy0, z0 = (int)fz0;
        const float* dc = dp + (size_t)cam * NPIX * DBINS;
        #pragma unroll
        for (int dy = 0; dy < 2; dy++)
            #pragma unroll
            for (int dx = 0; dx < 2; dx++) {
                const int xi = x0 + dx, yi = y0 + dy;
                if ((unsigned)xi < 88u && (unsigned)yi < 32u) {
                    const float wxy = (dx ? fx : 1.f-fx) * (dy ? fy : 1.f-fy);
                    const float* dr = dc + (size_t)(yi*88 + xi) * DBINS;
                    #pragma unroll
                    for (int dz = 0; dz < 2; dz++) {
                        const int zi = z0 + dz;
                        const float wv = wxy * (dz ? fz : 1.f-fz);
                        if ((unsigned)zi < 112u) { agg += wv * dr[zi]; mask += wv; }
                    }
                }
            }
    }
    out[v] = (mask > 0.f) ? (agg / mask) : agg;
}

extern "C" void kernel_launch(void* const* d_in, const int* in_sizes, int n_in,
                              void* d_out, int out_size)
{
    const float* img    = (const float*)d_in[0];
    const float* intr   = (const float*)d_in[1];
    const float* grid   = (const float*)d_in[2];
    const float* red_w  = (const float*)d_in[3];
    const float* red_s  = (const float*)d_in[4];
    const float* red_b  = (const float*)d_in[5];
    const float* mlp_w1 = (const float*)d_in[6];
    const float* mlp_b1 = (const float*)d_in[7];
    const float* mlp_w2 = (const float*)d_in[8];
    const float* mlp_b2 = (const float*)d_in[9];
    const float* se_rw  = (const float*)d_in[10];
    const float* se_rb  = (const float*)d_in[11];
    const float* se_ew  = (const float*)d_in[12];
    const float* se_eb  = (const float*)d_in[13];
    const float* bb_w   = (const float*)d_in[14];
    const float* bb_s   = (const float*)d_in[15];
    const float* bb_b   = (const float*)d_in[16];
    const float* dp_w   = (const float*)d_in[17];
    const float* dp_b   = (const float*)d_in[18];

    float *pdp, *pg;
    __nv_bfloat16 *pih, *pil, *pxh, *pxl, *pyh, *pyl;
    cudaGetSymbolAddress((void**)&pdp, g_dp);
    cudaGetSymbolAddress((void**)&pg,  g_gate);
    cudaGetSymbolAddress((void**)&pih, g_imgh);
    cudaGetSymbolAddress((void**)&pil, g_imgl);
    cudaGetSymbolAddress((void**)&pxh, g_xh);
    cudaGetSymbolAddress((void**)&pxl, g_xl);
    cudaGetSymbolAddress((void**)&pyh, g_yh);
    cudaGetSymbolAddress((void**)&pyl, g_yl);

    cudaFuncSetAttribute(conv_kernel<512,0>, cudaFuncAttributeMaxDynamicSharedMemorySize, CONV_SMEM);
    cudaFuncSetAttribute(conv_kernel<256,1>, cudaFuncAttributeMaxDynamicSharedMemorySize, CONV_SMEM);
    cudaFuncSetAttribute(conv_kernel<256,2>, cudaFuncAttributeMaxDynamicSharedMemorySize, CONV_SMEM);
    cudaFuncSetAttribute(logit_softmax_kernel, cudaFuncAttributeMaxDynamicSharedMemorySize, LG_SMEM);
    cudaFuncSetAttribute(wtrans2_kernel<512>, cudaFuncAttributeMaxDynamicSharedMemorySize, 73728);
    cudaFuncSetAttribute(wtrans2_kernel<256>, cudaFuncAttributeMaxDynamicSharedMemorySize, 73728);

    gate_kernel<<<NCAM, 256>>>(intr, mlp_w1, mlp_b1, mlp_w2, mlp_b2,
                               se_rw, se_rb, se_ew, se_eb, pg);
    prep_img_kernel<<<dim3(22, 8, NCAM), 256>>>(img);
    wtrans2_kernel<512><<<dim3(64, 1), 256, 73728>>>(red_w, 0);
    wtrans2_kernel<256><<<dim3(32, 6), 256, 73728>>>(bb_w, 144);
    dtrans_kernel<<<64, 256>>>(dp_w);

    dim3 cg(22, 1, NCAM);
    conv_kernel<512,0><<<cg, 512, CONV_SMEM>>>(pih, pil, 0, red_s, red_b, pg,
                                               nullptr, nullptr, pxh, pxl);
    for (int i = 0; i < 3; i++) {
        conv_kernel<256,1><<<cg, 512, CONV_SMEM>>>(pxh, pxl, 144 + (2*i)*72,
            bb_s + (2*i)*MID, bb_b + (2*i)*MID, nullptr, nullptr, nullptr, pyh, pyl);
        conv_kernel<256,2><<<cg, 512, CONV_SMEM>>>(pyh, pyl, 144 + (2*i+1)*72,
            bb_s + (2*i+1)*MID, bb_b + (2*i+1)*MID, nullptr, pxh, pxl, pxh, pxl);
    }
    logit_softmax_kernel<<<cg, 256, LG_SMEM>>>(pxh, pxl, dp_b, pdp);
    sample_kernel<<<(NVOX + 255)/256, 256>>>(grid, pdp, (float*)d_out);
}